// round 17
// baseline (speedup 1.0000x reference)
#include <cuda_runtime.h>
#include <cuda_bf16.h>
#include <cstdint>

#define B_ROWS 32768
#define C_COLS 1000
#define C_PAD  1024
#define FDIM   256

#define TM   32                // rows per CTA (cos tile fully register-resident)
#define KSL  32                // K-slice width
#define NKSL (FDIM / KSL)      // 8
#define NBUF 3                 // triple buffering
#define THREADS 512            // 16 warps, each owns 64 cols (8 n-blocks of 8)
#define CLUSTER 2              // paired CTAs share B via multicast

#define APAD   264             // A: 256 + 8 bf16 pad -> conflict-free ldmatrix
#define ROWB   (APAD * 2)      // 528 B per A smem row
#define A_BYTES (TM * ROWB)    // 16896
// B slice in SMEM: 16 warp regions of 32 k-rows x 128B (4KB), bytes arrive
// pre-swizzled from gmem (swizzle baked by prep kernel) via linear bulk copies
#define B_SLICE (C_PAD * KSL * 2)           // 65536 per buffer
#define RS_OFF  (A_BYTES + NBUF * B_SLICE)  // 213504
#define MBAR_OFF (RS_OFF + TM * 4)          // 213632
#define SMEM_TOTAL (MBAR_OFF + 16 * NBUF * 16)   // 214400 (1 CTA/SM)

// ---- scratch: B pre-tiled+swizzled: [ks][warp] 4KB blocks, SMEM byte order --
__device__ __nv_bfloat16 g_pbs[NKSL * 16 * 2048];   // 512 KB

// ---- helpers ----------------------------------------------------------------
__device__ __forceinline__ uint32_t smem_u32(const void* p) {
    uint32_t a;
    asm("{ .reg .u64 t; cvta.to.shared.u64 t, %1; cvt.u32.u64 %0, t; }" : "=r"(a) : "l"(p));
    return a;
}
__device__ __forceinline__ void ldsm4(uint32_t* r, uint32_t addr) {
    asm volatile("ldmatrix.sync.aligned.m8n8.x4.shared.b16 {%0,%1,%2,%3}, [%4];"
                 : "=r"(r[0]), "=r"(r[1]), "=r"(r[2]), "=r"(r[3]) : "r"(addr));
}
__device__ __forceinline__ void ldsm4t(uint32_t* r, uint32_t addr) {
    asm volatile("ldmatrix.sync.aligned.m8n8.x4.trans.shared.b16 {%0,%1,%2,%3}, [%4];"
                 : "=r"(r[0]), "=r"(r[1]), "=r"(r[2]), "=r"(r[3]) : "r"(addr));
}
__device__ __forceinline__ void mma16816(float* c, const uint32_t* a, uint32_t b0, uint32_t b1) {
    asm volatile(
        "mma.sync.aligned.m16n8k16.row.col.f32.bf16.bf16.f32 "
        "{%0,%1,%2,%3}, {%4,%5,%6,%7}, {%8,%9}, {%0,%1,%2,%3};"
        : "+f"(c[0]), "+f"(c[1]), "+f"(c[2]), "+f"(c[3])
        : "r"(a[0]), "r"(a[1]), "r"(a[2]), "r"(a[3]), "r"(b0), "r"(b1));
}
__device__ __forceinline__ void mbar_init(uint32_t a, uint32_t cnt) {
    asm volatile("mbarrier.init.shared.b64 [%0], %1;" :: "r"(a), "r"(cnt) : "memory");
}
__device__ __forceinline__ void mbar_expect_tx(uint32_t a, uint32_t bytes) {
    asm volatile("mbarrier.arrive.expect_tx.shared.b64 _, [%0], %1;"
                 :: "r"(a), "r"(bytes) : "memory");
}
__device__ __forceinline__ void mbar_arrive(uint32_t a) {
    asm volatile("mbarrier.arrive.shared.b64 _, [%0];" :: "r"(a) : "memory");
}
__device__ __forceinline__ void mbar_arrive_remote(uint32_t a, uint32_t peer) {
    asm volatile(
        "{\n\t.reg .b32 ra;\n\t"
        "mapa.shared::cluster.u32 ra, %0, %1;\n\t"
        "mbarrier.arrive.shared::cluster.b64 _, [ra];\n\t}"
        :: "r"(a), "r"(peer) : "memory");
}
__device__ __forceinline__ void mbar_wait(uint32_t a, uint32_t parity) {
    asm volatile(
        "{\n\t.reg .pred P1;\n\t"
        "WAIT_%=:\n\t"
        "mbarrier.try_wait.parity.acquire.cta.shared::cta.b64 P1, [%0], %1, 0x989680;\n\t"
        "@P1 bra.uni DONE_%=;\n\t"
        "bra.uni WAIT_%=;\n\t"
        "DONE_%=:\n\t}"
        :: "r"(a), "r"(parity) : "memory");
}
__device__ __forceinline__ void bulk_mc(uint32_t dst, const void* src, uint32_t bytes,
                                        uint32_t mbar, uint16_t mask) {
    asm volatile(
        "cp.async.bulk.shared::cluster.global.mbarrier::complete_tx::bytes.multicast::cluster"
        " [%0], [%1], %2, [%3], %4;"
        :: "r"(dst), "l"(src), "r"(bytes), "r"(mbar), "h"(mask) : "memory");
}
#define CLUSTER_SYNC() do { \
    asm volatile("barrier.cluster.arrive.aligned;" ::: "memory"); \
    asm volatile("barrier.cluster.wait.aligned;" ::: "memory"); \
} while (0)

// ---------------------------------------------------------------------------
// Prototype prep: normalize + bf16 + tile/swizzle into g_pbs.
// Block = 32 cols. Dest byte layout per (ks,warp) 4KB block =
// kk*128 + ((seg ^ (kk&7))<<4) + inner  -> exactly SMEM consumer order.
// ---------------------------------------------------------------------------
__global__ void __launch_bounds__(256) prep_proto_kernel(const float* __restrict__ x) {
    __shared__ __nv_bfloat16 tile[32][APAD];
    const int c0   = blockIdx.x * 32;
    const int wid  = threadIdx.x >> 5;
    const int lane = threadIdx.x & 31;

#pragma unroll
    for (int rr = 0; rr < 4; rr++) {
        int cl = wid * 4 + rr;
        int c  = c0 + cl;
        float4 a = make_float4(0.f, 0.f, 0.f, 0.f);
        float4 b = make_float4(0.f, 0.f, 0.f, 0.f);
        if (c < C_COLS) {
            const float4* r4 = reinterpret_cast<const float4*>(x + (size_t)c * FDIM);
            a = r4[lane * 2]; b = r4[lane * 2 + 1];
        }
        float s = a.x*a.x + a.y*a.y + a.z*a.z + a.w*a.w + b.x*b.x + b.y*b.y + b.z*b.z + b.w*b.w;
#pragma unroll
        for (int o = 16; o; o >>= 1) s += __shfl_xor_sync(0xffffffffu, s, o);
        float inv = 1.0f / fmaxf(sqrtf(s), 1e-12f);
        __nv_bfloat162 p0 = __floats2bfloat162_rn(a.x*inv, a.y*inv);
        __nv_bfloat162 p1 = __floats2bfloat162_rn(a.z*inv, a.w*inv);
        __nv_bfloat162 p2 = __floats2bfloat162_rn(b.x*inv, b.y*inv);
        __nv_bfloat162 p3 = __floats2bfloat162_rn(b.z*inv, b.w*inv);
        uint4 o4;
        o4.x = *reinterpret_cast<uint32_t*>(&p0); o4.y = *reinterpret_cast<uint32_t*>(&p1);
        o4.z = *reinterpret_cast<uint32_t*>(&p2); o4.w = *reinterpret_cast<uint32_t*>(&p3);
        *reinterpret_cast<uint4*>(&tile[cl][lane * 8]) = o4;
    }
    __syncthreads();

    const uint16_t* t16 = reinterpret_cast<const uint16_t*>(tile);
    char* dst = reinterpret_cast<char*>(g_pbs);
#pragma unroll
    for (int it = 0; it < 16; it++) {
        int idx = threadIdx.x + it * 256;        // 0..4095
        int k   = idx >> 4;                      // 0..255
        int cp  = idx & 15;                      // col-pair 0..15
        int c   = c0 + 2 * cp;
        uint32_t lo = t16[(2 * cp)     * APAD + k];
        uint32_t hi = t16[(2 * cp + 1) * APAD + k];
        int ks = k >> 5, kk = k & 31;
        int w  = c >> 6;
        int sg = (c & 63) >> 3;
        size_t off = (((size_t)(ks * 16 + w)) << 12)
                   + ((size_t)kk << 7)
                   + (((size_t)(sg ^ (kk & 7))) << 4)
                   + (size_t)((c & 7) * 2);
        *reinterpret_cast<uint32_t*>(dst + off) = lo | (hi << 16);
    }
}

// ---------------------------------------------------------------------------
// Fused single-pass GEMM, cluster-of-2 multicast B: each CTA loads HALF of
// each warp-slice (2KB) and multicasts; per-warp mbarrier pipelines (full:
// expect 4KB from both halves; empty: 2 arrivals local+peer). Warp-local sync.
// ---------------------------------------------------------------------------
__global__ void __launch_bounds__(THREADS, 1) __cluster_dims__(CLUSTER, 1, 1)
fused_kernel(
    const float* __restrict__ feats,
    const float* __restrict__ dscale,
    const float* __restrict__ temp,
    float* __restrict__ out)
{
    extern __shared__ char smem[];
    char*  smA = smem;
    float* rs  = reinterpret_cast<float*>(smem + RS_OFF);

    const uint32_t sbA  = smem_u32(smA);
    const uint32_t sbB  = sbA + A_BYTES;
    const uint32_t sbMB = sbA + MBAR_OFF;

    const int tid  = threadIdx.x;
    const int wid  = tid >> 5;         // 0..15
    const int lane = tid & 31;
    const int q    = lane >> 2;
    const int row0 = blockIdx.x * TM;

    uint32_t rank;
    asm("mov.u32 %0, %%cluster_ctarank;" : "=r"(rank));
    const uint32_t peer = rank ^ 1u;

    if (tid < TM) rs[tid] = 0.0f;
    if (tid < 16 * NBUF) {                       // full cnt=1, empty cnt=2
        mbar_init(sbMB + tid * 16, 1);
        mbar_init(sbMB + tid * 16 + 8, 2);
    }
    __syncthreads();
    CLUSTER_SYNC();                              // peer mbars live before multicast

    const char* pbs = reinterpret_cast<const char*>(g_pbs);
    const uint32_t wOff = (uint32_t)(wid * 4096);
    const uint32_t hOff = rank * 2048u;          // this CTA loads its half

    // prologue: slices 0..2 (lane 0 of each warp)
    if (lane == 0) {
#pragma unroll
        for (int ks = 0; ks < NBUF; ks++) {
            uint32_t fmb = sbMB + (uint32_t)((wid * NBUF + ks) * 16);
            mbar_expect_tx(fmb, 4096);
            bulk_mc(sbB + ks * B_SLICE + wOff + hOff,
                    pbs + (((size_t)(ks * 16 + wid)) << 12) + hOff,
                    2048, fmb, (uint16_t)0x3);
        }
    }

    // ---- A tile: load fp32, normalize, convert, store bf16 (warp per row) ----
    const float4* f4 = reinterpret_cast<const float4*>(feats);
#pragma unroll
    for (int rr = 0; rr < TM / 16; rr++) {
        int r = wid + rr * 16;
        float4 a = f4[(size_t)(row0 + r) * 64 + lane * 2];
        float4 b = f4[(size_t)(row0 + r) * 64 + lane * 2 + 1];
        float sn = a.x*a.x + a.y*a.y + a.z*a.z + a.w*a.w + b.x*b.x + b.y*b.y + b.z*b.z + b.w*b.w;
#pragma unroll
        for (int o = 16; o; o >>= 1) sn += __shfl_xor_sync(0xffffffffu, sn, o);
        float inv = 1.0f / fmaxf(sqrtf(sn), 1e-12f);
        __nv_bfloat162 p0 = __floats2bfloat162_rn(a.x*inv, a.y*inv);
        __nv_bfloat162 p1 = __floats2bfloat162_rn(a.z*inv, a.w*inv);
        __nv_bfloat162 p2 = __floats2bfloat162_rn(b.x*inv, b.y*inv);
        __nv_bfloat162 p3 = __floats2bfloat162_rn(b.z*inv, b.w*inv);
        uint4 o4;
        o4.x = *reinterpret_cast<uint32_t*>(&p0); o4.y = *reinterpret_cast<uint32_t*>(&p1);
        o4.z = *reinterpret_cast<uint32_t*>(&p2); o4.w = *reinterpret_cast<uint32_t*>(&p3);
        *reinterpret_cast<uint4*>(smA + r * ROWB + lane * 16) = o4;
    }
    __syncthreads();   // A tile + rs init visible

    const uint32_t aBase = sbA + (uint32_t)((lane & 15) * APAD + ((lane >> 4) << 3)) * 2;
    const uint32_t bRow  = wOff + (uint32_t)(lane * 128);
    const int l8 = lane & 7;

    float acc[8][2][4];
#pragma unroll
    for (int j = 0; j < 8; j++)
#pragma unroll
        for (int i = 0; i < 2; i++)
#pragma unroll
            for (int c = 0; c < 4; c++) acc[j][i][c] = 0.0f;

#pragma unroll
    for (int ks = 0; ks < NKSL; ks++) {
        const int buf = ks % NBUF;
        const int par = (ks / NBUF) & 1;
        const uint32_t fmb = sbMB + (uint32_t)((wid * NBUF + buf) * 16);
        const uint32_t emb = fmb + 8;

        mbar_wait(fmb, (uint32_t)par);           // both halves of slice ks landed
        __syncwarp();

        uint32_t A00[4], A01[4], A10[4], A11[4];
        ldsm4(A00, aBase + (ks * KSL) * 2);
        ldsm4(A01, aBase + (ks * KSL + 16) * 2);
        ldsm4(A10, aBase + 16 * ROWB + (ks * KSL) * 2);
        ldsm4(A11, aBase + 16 * ROWB + (ks * KSL + 16) * 2);

        const uint32_t bBase = sbB + buf * B_SLICE + bRow;

#pragma unroll
        for (int j = 0; j < 8; j++) {
            uint32_t b[4];
            ldsm4t(b, bBase + (uint32_t)((j ^ l8) << 4));
            mma16816(acc[j][0], A00, b[0], b[1]);
            mma16816(acc[j][1], A10, b[0], b[1]);
            mma16816(acc[j][0], A01, b[2], b[3]);
            mma16816(acc[j][1], A11, b[2], b[3]);
        }
        __syncwarp();                            // all lanes' reads of buf done

        if (lane == 0) {
            mbar_arrive(emb);                    // local consumption done
            mbar_arrive_remote(emb, peer);       // tell peer's empty too
            if (ks + NBUF < NKSL) {
                mbar_wait(emb, (uint32_t)par);   // both CTAs' warps released buf
                mbar_expect_tx(fmb, 4096);
                bulk_mc(sbB + buf * B_SLICE + wOff + hOff,
                        pbs + (((size_t)((ks + NBUF) * 16 + wid)) << 12) + hOff,
                        2048, fmb, (uint16_t)0x3);
            }
        }
    }

    // ---- iso in place + per-row partial sums ----
    const float s = fabsf(__ldg(dscale));
    float rsum[4] = {0.f, 0.f, 0.f, 0.f};
#pragma unroll
    for (int j = 0; j < 8; j++) {
        int col = wid * 64 + j * 8 + (lane & 3) * 2;
#pragma unroll
        for (int i = 0; i < 2; i++) {
            if (col < C_COLS) {
                float* a = acc[j][i];
                a[0] = s * sqrtf(fmaxf(1.0f - a[0], 0.0f));
                a[1] = s * sqrtf(fmaxf(1.0f - a[1], 0.0f));
                a[2] = s * sqrtf(fmaxf(1.0f - a[2], 0.0f));
                a[3] = s * sqrtf(fmaxf(1.0f - a[3], 0.0f));
                rsum[2 * i]     += a[0] + a[1];
                rsum[2 * i + 1] += a[2] + a[3];
            }
        }
    }

#pragma unroll
    for (int k = 0; k < 4; k++) {
        float v = rsum[k];
        v += __shfl_xor_sync(0xffffffffu, v, 1);
        v += __shfl_xor_sync(0xffffffffu, v, 2);
        if ((lane & 3) == 0) {
            int rloc = 16 * (k >> 1) + 8 * (k & 1) + q;
            atomicAdd(&rs[rloc], v);
        }
    }
    __syncthreads();

    // ---- final store: logits = -(iso + mean)/T, straight from registers ----
    const float itT = 1.0f / __ldg(temp);
    float mean[4];
#pragma unroll
    for (int k = 0; k < 4; k++)
        mean[k] = rs[16 * (k >> 1) + 8 * (k & 1) + q] * (1.0f / (float)C_COLS);

#pragma unroll
    for (int j = 0; j < 8; j++) {
        int col = wid * 64 + j * 8 + (lane & 3) * 2;
#pragma unroll
        for (int i = 0; i < 2; i++) {
            if (col < C_COLS) {
                int r0 = row0 + 16 * i + q;
                const float* a = acc[j][i];
                float2 v0 = make_float2(-(a[0] + mean[2*i])     * itT,
                                        -(a[1] + mean[2*i])     * itT);
                float2 v1 = make_float2(-(a[2] + mean[2*i + 1]) * itT,
                                        -(a[3] + mean[2*i + 1]) * itT);
                *reinterpret_cast<float2*>(&out[(size_t)r0 * C_COLS + col])       = v0;
                *reinterpret_cast<float2*>(&out[(size_t)(r0 + 8) * C_COLS + col]) = v1;
            }
        }
    }

    CLUSTER_SYNC();    // no CTA exits while peer multicasts/arrives may target it
}

// ---------------------------------------------------------------------------
extern "C" void kernel_launch(void* const* d_in, const int* in_sizes, int n_in,
                              void* d_out, int out_size)
{
    const float* feats  = (const float*)d_in[0];
    const float* protos = (const float*)d_in[1];
    const float* ds     = (const float*)d_in[2];
    const float* temp   = (const float*)d_in[3];
    float* out = (float*)d_out;

    cudaFuncSetAttribute(fused_kernel,
                         cudaFuncAttributeMaxDynamicSharedMemorySize, SMEM_TOTAL);

    prep_proto_kernel<<<C_PAD / 32, 256>>>(protos);
    fused_kernel<<<B_ROWS / TM, THREADS, SMEM_TOTAL>>>(feats, ds, temp, out);
}